// round 7
// baseline (speedup 1.0000x reference)
#include <cuda_runtime.h>

// Problem constants (fixed shapes)
#define NN   50000
#define EE   640000
#define DIN  64
#define GB_  128
#define GD_  4
#define LB_  256
#define LD_  2
#define GG   1024

typedef unsigned long long ull;

// ---------------- device scratch ----------------
__device__ __align__(16) float d_dinv[NN];
__device__ int   d_ideg[NN];
__device__ int   d_off[NN + 1];
__device__ int   d_cursor[NN];
__device__ int   d_srcA[EE];
__device__ int   d_dstA[EE];
__device__ __align__(16) int2  d_csr[EE];      // {src, float_bits(enorm)}
__device__ __align__(16) float d_aggx[(size_t)NN * DIN];
__device__ __align__(16) float d_hw [(size_t)NN * GB_];
__device__ __align__(16) float d_agg[(size_t)NN * GB_];   // h (layer0/1 in) or BN pre-activations
__device__ __align__(16) float d_stats[2 * GB_];
__device__ __align__(16) float d_scale[GB_];
__device__ __align__(16) float d_shift[GB_];
__device__ __align__(16) float d_hp[GG * GB_];
__device__ __align__(16) float d_l0[GG * LB_];
__device__ __align__(16) float d_l1[GG * LB_];
__device__ __align__(16) float d_lscale[LB_];
__device__ __align__(16) float d_lshift[LB_];
__device__ int d_is64;

// ---------------- helpers ----------------
__device__ __forceinline__ void red_add_v4(float* p, float a, float b, float c, float d) {
    asm volatile("red.global.add.v4.f32 [%0], {%1, %2, %3, %4};"
                 :: "l"(p), "f"(a), "f"(b), "f"(c), "f"(d) : "memory");
}
__device__ __forceinline__ ull ffma2(ull a, ull b, ull c) {
    ull r;
    asm("fma.rn.f32x2 %0, %1, %2, %3;" : "=l"(r) : "l"(a), "l"(b), "l"(c));
    return r;
}
__device__ __forceinline__ float2 unpack2(ull v) {
    float2 r;
    asm("mov.b64 {%0, %1}, %2;" : "=f"(r.x), "=f"(r.y) : "l"(v));
    return r;
}

// ---------------- preprocessing ----------------
// fused: dtype detect (1 thread) + degree init
__global__ void k_detect_init(const int* __restrict__ ei32) {
    int n = blockIdx.x * blockDim.x + threadIdx.x;
    if (n < NN) d_ideg[n] = 0;
    if (blockIdx.x == 0 && threadIdx.x == 0) {
        int zeros = 0;
        for (int i = 0; i < 64; i++)
            if (ei32[2 * i + 1] == 0) zeros++;
        d_is64 = (zeros >= 60) ? 1 : 0;
    }
}

__global__ void k_prep_edges(const void* __restrict__ ei) {
    int e = blockIdx.x * blockDim.x + threadIdx.x;
    if (e < EE) {
        int s, d;
        if (d_is64) {
            const long long* p = (const long long*)ei;
            s = (int)p[e];
            d = (int)p[EE + e];
        } else {
            const int* p = (const int*)ei;
            s = p[e];
            d = p[EE + e];
        }
        s = min(max(s, 0), NN - 1);
        d = min(max(d, 0), NN - 1);
        d_srcA[e] = s;
        d_dstA[e] = d;
        atomicAdd(&d_ideg[d], 1);
    }
}

__global__ void k_finish_dinv() {
    int n = blockIdx.x * blockDim.x + threadIdx.x;
    if (n < NN) d_dinv[n] = rsqrtf((float)(1 + d_ideg[n]));
}

// single-block exclusive scan of d_ideg -> d_off (+ cursor copy)
__global__ __launch_bounds__(1024) void k_scan() {
    __shared__ int wsum[32];
    __shared__ int s_carry;
    int t = threadIdx.x, lane = t & 31, wid = t >> 5;
    if (t == 0) s_carry = 0;
    __syncthreads();
    for (int base = 0; base < NN; base += 1024) {
        int v = (base + t < NN) ? d_ideg[base + t] : 0;
        int x = v;
        #pragma unroll
        for (int o = 1; o < 32; o <<= 1) {
            int y = __shfl_up_sync(0xffffffffu, x, o);
            if (lane >= o) x += y;
        }
        if (lane == 31) wsum[wid] = x;
        __syncthreads();
        if (wid == 0) {
            int y = wsum[lane];
            #pragma unroll
            for (int o = 1; o < 32; o <<= 1) {
                int z = __shfl_up_sync(0xffffffffu, y, o);
                if (lane >= o) y += z;
            }
            wsum[lane] = y;
        }
        __syncthreads();
        int excl = s_carry + (wid > 0 ? wsum[wid - 1] : 0) + x - v;
        if (base + t < NN) { d_off[base + t] = excl; d_cursor[base + t] = excl; }
        __syncthreads();
        if (t == 0) s_carry += wsum[31];
        __syncthreads();
    }
    if (t == 0) d_off[NN] = s_carry;
}

__global__ void k_csr_fill() {
    int e = blockIdx.x * blockDim.x + threadIdx.x;
    if (e < EE) {
        int s = d_srcA[e], d = d_dstA[e];
        int pos = atomicAdd(&d_cursor[d], 1);
        float w = d_dinv[s] * d_dinv[d];
        d_csr[pos] = make_int2(s, __float_as_int(w));
    }
}

// ---------------- layer-0 aggregation on raw x (64 wide): aggx[n] = sum_in x[s]*w + x[n]*snorm
__global__ __launch_bounds__(256) void k_aggx(const float* __restrict__ x) {
    int n = blockIdx.x * 8 + (threadIdx.x >> 5);
    if (n >= NN) return;
    int lane = threadIdx.x & 31;
    float sn = __ldg(&d_dinv[n]);
    float sn2 = sn * sn;
    float2 vs = __ldg((const float2*)(x + (size_t)n * DIN) + lane);
    float2 acc = make_float2(vs.x * sn2, vs.y * sn2);

    int o0 = __ldg(&d_off[n]), o1 = __ldg(&d_off[n + 1]);
    int2 e0 = make_int2(0, 0), e1 = make_int2(0, 0);
    if (o0 < o1)     e0 = __ldg(&d_csr[o0]);
    if (o0 + 1 < o1) e1 = __ldg(&d_csr[o0 + 1]);
    for (int e = o0; e < o1; e++) {
        int2 e2 = make_int2(0, 0);
        if (e + 2 < o1) e2 = __ldg(&d_csr[e + 2]);
        float w = __int_as_float(e0.y);
        float2 v = __ldg((const float2*)(x + (size_t)e0.x * DIN) + lane);
        acc.x += v.x * w; acc.y += v.y * w;
        e0 = e1; e1 = e2;
    }
    *((float2*)(d_aggx + (size_t)n * DIN) + lane) = acc;
}

// ---------------- node GEMM: out[N,128] = f(in)[N,K] @ W[K,128]  (FFMA2, dup-weight smem) ----
// INBN: apply scale/shift+relu to input while loading. EPI: add bias + relu on output.
template <int K, bool INBN, bool EPI>
__global__ __launch_bounds__(256) void k_gemm(const float* __restrict__ h,
                                              const float* __restrict__ W,
                                              const float* __restrict__ bias,
                                              float* __restrict__ out) {
    extern __shared__ float sm[];
    float* ws = sm;             // [K][256] duplicated pairs
    float* hs = sm + K * 256;   // [K][64]  transposed h tile
    int t = threadIdx.x;
    int row0 = blockIdx.x * 64;

    // weights: duplicate each element into an adjacent pair
    for (int i = t; i < K * 128; i += 256) {
        int k = i >> 7, c = i & 127;
        float w = W[i];
        *(float2*)&ws[k * 256 + 2 * c] = make_float2(w, w);
    }
    // h tile transposed: hs[k][row]
    for (int i = t; i < 64 * (K / 4); i += 256) {
        int row = i & 63;
        int kq = i >> 6;              // k/4
        int grow = row0 + row;
        if (grow < NN) {
            float4 v = *(const float4*)(h + (size_t)grow * K + 4 * kq);
            if (INBN) {
                float4 sc = *(const float4*)&d_scale[4 * kq];
                float4 sh = *(const float4*)&d_shift[4 * kq];
                v.x = fmaxf(v.x * sc.x + sh.x, 0.0f);
                v.y = fmaxf(v.y * sc.y + sh.y, 0.0f);
                v.z = fmaxf(v.z * sc.z + sh.z, 0.0f);
                v.w = fmaxf(v.w * sc.w + sh.w, 0.0f);
            }
            hs[(4 * kq + 0) * 64 + row] = v.x;
            hs[(4 * kq + 1) * 64 + row] = v.y;
            hs[(4 * kq + 2) * 64 + row] = v.z;
            hs[(4 * kq + 3) * 64 + row] = v.w;
        }
    }
    __syncthreads();

    int warp = t >> 5, lane = t & 31;
    int wr0 = warp * 8;
    // acc[p][c]: f32x2 over row pair (wr0+2p, wr0+2p+1), col (lane + 32c)
    ull acc[4][4] = {};
    #pragma unroll 4
    for (int k = 0; k < K; k++) {
        ull w0 = *(const ull*)&ws[k * 256 + 2 * lane];
        ull w1 = *(const ull*)&ws[k * 256 + 2 * lane + 64];
        ull w2 = *(const ull*)&ws[k * 256 + 2 * lane + 128];
        ull w3 = *(const ull*)&ws[k * 256 + 2 * lane + 192];
        ull h0 = *(const ull*)&hs[k * 64 + wr0];
        ull h1 = *(const ull*)&hs[k * 64 + wr0 + 2];
        ull h2 = *(const ull*)&hs[k * 64 + wr0 + 4];
        ull h3 = *(const ull*)&hs[k * 64 + wr0 + 6];
        acc[0][0] = ffma2(h0, w0, acc[0][0]); acc[0][1] = ffma2(h0, w1, acc[0][1]);
        acc[0][2] = ffma2(h0, w2, acc[0][2]); acc[0][3] = ffma2(h0, w3, acc[0][3]);
        acc[1][0] = ffma2(h1, w0, acc[1][0]); acc[1][1] = ffma2(h1, w1, acc[1][1]);
        acc[1][2] = ffma2(h1, w2, acc[1][2]); acc[1][3] = ffma2(h1, w3, acc[1][3]);
        acc[2][0] = ffma2(h2, w0, acc[2][0]); acc[2][1] = ffma2(h2, w1, acc[2][1]);
        acc[2][2] = ffma2(h2, w2, acc[2][2]); acc[2][3] = ffma2(h2, w3, acc[2][3]);
        acc[3][0] = ffma2(h3, w0, acc[3][0]); acc[3][1] = ffma2(h3, w1, acc[3][1]);
        acc[3][2] = ffma2(h3, w2, acc[3][2]); acc[3][3] = ffma2(h3, w3, acc[3][3]);
    }

    float bb[4];
    if (EPI) {
        bb[0] = bias[lane]; bb[1] = bias[lane + 32];
        bb[2] = bias[lane + 64]; bb[3] = bias[lane + 96];
    }
    #pragma unroll
    for (int p = 0; p < 4; p++) {
        int r0 = row0 + wr0 + 2 * p;
        int r1 = r0 + 1;
        #pragma unroll
        for (int c = 0; c < 4; c++) {
            float2 v = unpack2(acc[p][c]);
            int cc = lane + 32 * c;
            if (EPI) {
                v.x = fmaxf(v.x + bb[c], 0.0f);
                v.y = fmaxf(v.y + bb[c], 0.0f);
            }
            if (r0 < NN) out[(size_t)r0 * 128 + cc] = v.x;
            if (r1 < NN) out[(size_t)r1 * 128 + cc] = v.y;
        }
    }
}

// ---------------- CSR aggregation (128-wide): pre[n] = sum_in hw[src]*w + hw[n]*snorm + b
// writes pre into d_agg + accumulates BN column stats
__global__ __launch_bounds__(256) void k_agg(const float* __restrict__ bias) {
    __shared__ float ss[128], sq[128];
    int t = threadIdx.x, lane = t & 31, warp = t >> 5;
    if (t < 128) { ss[t] = 0.f; sq[t] = 0.f; }
    __syncthreads();
    float4 bias4 = __ldg((const float4*)bias + lane);
    float4 sum4 = {0, 0, 0, 0}, sq4 = {0, 0, 0, 0};

    int n0 = (blockIdx.x * 8 + warp) * 8;
    for (int j = 0; j < 8; j++) {
        int n = n0 + j;
        if (n >= NN) break;
        float4 acc = bias4;
        int o0 = __ldg(&d_off[n]), o1 = __ldg(&d_off[n + 1]);
        int2 e0 = make_int2(0, 0), e1 = make_int2(0, 0);
        if (o0 < o1)     e0 = __ldg(&d_csr[o0]);
        if (o0 + 1 < o1) e1 = __ldg(&d_csr[o0 + 1]);
        for (int e = o0; e < o1; e++) {
            int2 e2 = make_int2(0, 0);
            if (e + 2 < o1) e2 = __ldg(&d_csr[e + 2]);
            float w = __int_as_float(e0.y);
            float4 v = __ldg((const float4*)(d_hw + (size_t)e0.x * 128) + lane);
            acc.x += v.x * w; acc.y += v.y * w; acc.z += v.z * w; acc.w += v.w * w;
            e0 = e1; e1 = e2;
        }
        float sn = __ldg(&d_dinv[n]);
        float sn2 = sn * sn;
        float4 vs = *((const float4*)(d_hw + (size_t)n * 128) + lane);
        acc.x += vs.x * sn2; acc.y += vs.y * sn2; acc.z += vs.z * sn2; acc.w += vs.w * sn2;

        *((float4*)(d_agg + (size_t)n * 128) + lane) = acc;
        sum4.x += acc.x; sum4.y += acc.y; sum4.z += acc.z; sum4.w += acc.w;
        sq4.x += acc.x * acc.x; sq4.y += acc.y * acc.y;
        sq4.z += acc.z * acc.z; sq4.w += acc.w * acc.w;
    }
    int c = lane * 4;
    atomicAdd(&ss[c + 0], sum4.x); atomicAdd(&ss[c + 1], sum4.y);
    atomicAdd(&ss[c + 2], sum4.z); atomicAdd(&ss[c + 3], sum4.w);
    atomicAdd(&sq[c + 0], sq4.x);  atomicAdd(&sq[c + 1], sq4.y);
    atomicAdd(&sq[c + 2], sq4.z);  atomicAdd(&sq[c + 3], sq4.w);
    __syncthreads();
    if (t < 128) {
        atomicAdd(&d_stats[t], ss[t]);
        atomicAdd(&d_stats[128 + t], sq[t]);
    }
}

__global__ void k_bn_params(const float* __restrict__ gamma, const float* __restrict__ beta) {
    int c = threadIdx.x;  // 128 threads
    float m = d_stats[c] * (1.0f / NN);
    float v = d_stats[128 + c] * (1.0f / NN) - m * m;
    float sc = gamma[c] * rsqrtf(v + 1e-5f);
    d_scale[c] = sc;
    d_shift[c] = beta[c] - m * sc;
}

// ---------------- fused BN-apply + pooling (final GCN layer) ----------------
__global__ __launch_bounds__(256) void k_bnpool(const void* __restrict__ batch) {
    int n = blockIdx.x * 8 + (threadIdx.x >> 5);
    if (n >= NN) return;
    int lane = threadIdx.x & 31;
    int g;
    if (d_is64) g = (int)((const long long*)batch)[n];
    else        g = ((const int*)batch)[n];
    g = min(max(g, 0), GG - 1);
    int c = lane * 4;
    float4 sc = *(const float4*)&d_scale[c];
    float4 sh = *(const float4*)&d_shift[c];
    float4 v = *((const float4*)(d_agg + (size_t)n * 128) + lane);
    v.x = fmaxf(v.x * sc.x + sh.x, 0.f);
    v.y = fmaxf(v.y * sc.y + sh.y, 0.f);
    v.z = fmaxf(v.z * sc.z + sh.z, 0.f);
    v.w = fmaxf(v.w * sc.w + sh.w, 0.f);
    red_add_v4(d_hp + (size_t)g * 128 + c, v.x, v.y, v.z, v.w);
}

// ---------------- head layer 0: l0 = relu(hp @ Wl0 + bl0)  [1024,128]@[128,256] ----------------
__global__ __launch_bounds__(256) void k_head0(const float* __restrict__ W, const float* __restrict__ b) {
    __shared__ float in_s[8 * 128];
    int t = threadIdx.x;
    int g0 = blockIdx.x * 8;
    for (int i = t; i < (8 * 128) / 4; i += 256)
        ((float4*)in_s)[i] = ((const float4*)(d_hp + (size_t)g0 * 128))[i];
    __syncthreads();
    float acc[8] = {};
    for (int k = 0; k < 128; k++) {
        float w = W[k * 256 + t];
        #pragma unroll
        for (int r = 0; r < 8; r++) acc[r] += in_s[r * 128 + k] * w;
    }
    float bb = b[t];
    #pragma unroll
    for (int r = 0; r < 8; r++)
        d_l0[(size_t)(g0 + r) * 256 + t] = fmaxf(acc[r] + bb, 0.0f);
}

// ---------------- head GEMM: l1 = l0 @ W + b  [1024,256]@[256,256] ----------------
__global__ __launch_bounds__(256) void k_headgemm(const float* __restrict__ W, const float* __restrict__ b) {
    __shared__ float in_s[8 * 256];
    int t = threadIdx.x;
    int g0 = blockIdx.x * 8;
    for (int i = t; i < (8 * 256) / 4; i += 256)
        ((float4*)in_s)[i] = ((const float4*)(d_l0 + (size_t)g0 * 256))[i];
    __syncthreads();
    float acc[8] = {};
    for (int k = 0; k < 256; k++) {
        float w = W[k * 256 + t];
        #pragma unroll
        for (int r = 0; r < 8; r++) acc[r] += in_s[r * 256 + k] * w;
    }
    float bb = b[t];
    #pragma unroll
    for (int r = 0; r < 8; r++)
        d_l1[(size_t)(g0 + r) * 256 + t] = acc[r] + bb;
}

// ---------------- head BN: one block per column ----------------
__global__ __launch_bounds__(256) void k_lbn_stats(const float* __restrict__ gamma, const float* __restrict__ beta) {
    int c = blockIdx.x;
    int t = threadIdx.x;
    float ls = 0.f, lss = 0.f;
    for (int r = t; r < GG; r += 256) {
        float v = d_l1[(size_t)r * 256 + c];
        ls += v; lss += v * v;
    }
    __shared__ float ss[256], sq[256];
    ss[t] = ls; sq[t] = lss;
    __syncthreads();
    for (int o = 128; o > 0; o >>= 1) {
        if (t < o) { ss[t] += ss[t + o]; sq[t] += sq[t + o]; }
        __syncthreads();
    }
    if (t == 0) {
        float m = ss[0] * (1.0f / GG);
        float v = sq[0] * (1.0f / GG) - m * m;
        float sc = gamma[c] * rsqrtf(v + 1e-5f);
        d_lscale[c] = sc;
        d_lshift[c] = beta[c] - m * sc;
    }
}

__global__ void k_lbn_apply() {
    size_t idx = (size_t)blockIdx.x * 256 + threadIdx.x;
    if (idx < (size_t)GG * 256) {
        int c = (int)(idx & 255);
        d_l0[idx] = fmaxf(d_l1[idx] * d_lscale[c] + d_lshift[c], 0.0f);
    }
}

// ---------------- final: out = l0 @ Wout + bout  [1024,256]@[256,2] ----------------
__global__ __launch_bounds__(64) void k_final(const float* __restrict__ Wout,
                                              const float* __restrict__ bout,
                                              float* __restrict__ out) {
    int r = blockIdx.x;
    int warp = threadIdx.x >> 5;
    int lane = threadIdx.x & 31;
    float s = 0.f;
    for (int k = lane; k < 256; k += 32)
        s += d_l0[(size_t)r * 256 + k] * Wout[k * 2 + warp];
    #pragma unroll
    for (int o = 16; o > 0; o >>= 1) s += __shfl_down_sync(0xffffffffu, s, o);
    if (lane == 0) out[r * 2 + warp] = s + bout[warp];
}

// ---------------- launch ----------------
extern "C" void kernel_launch(void* const* d_in, const int* in_sizes, int n_in,
                              void* d_out, int out_size) {
    const float* x     = (const float*)d_in[0];
    const void*  ei    = d_in[1];
    const void*  batch = d_in[2];
    int base = (n_in >= 18) ? 4 : 3;
    const float* W0      = (const float*)d_in[base + 0];
    const float* b0      = (const float*)d_in[base + 1];
    const float* Wg      = (const float*)d_in[base + 2];
    const float* bg      = (const float*)d_in[base + 3];
    const float* gamma_g = (const float*)d_in[base + 4];
    const float* beta_g  = (const float*)d_in[base + 5];
    const float* Wl0     = (const float*)d_in[base + 6];
    const float* bl0     = (const float*)d_in[base + 7];
    const float* Wl      = (const float*)d_in[base + 8];
    const float* bl      = (const float*)d_in[base + 9];
    const float* gamma_l = (const float*)d_in[base + 10];
    const float* beta_l  = (const float*)d_in[base + 11];
    const float* Wout    = (const float*)d_in[base + 12];
    const float* bout    = (const float*)d_in[base + 13];

    void *p_stats, *p_hp, *p_agg, *p_hw, *p_aggx;
    cudaGetSymbolAddress(&p_stats, d_stats);
    cudaGetSymbolAddress(&p_hp, d_hp);
    cudaGetSymbolAddress(&p_agg, d_agg);
    cudaGetSymbolAddress(&p_hw, d_hw);
    cudaGetSymbolAddress(&p_aggx, d_aggx);

    const int SMEM64  = (64 * 256 + 64 * 64) * 4;     // 80 KB
    const int SMEM128 = (128 * 256 + 128 * 64) * 4;   // 160 KB
    cudaFuncSetAttribute(k_gemm<64,  false, true>,  cudaFuncAttributeMaxDynamicSharedMemorySize, SMEM64);
    cudaFuncSetAttribute(k_gemm<128, false, false>, cudaFuncAttributeMaxDynamicSharedMemorySize, SMEM128);
    cudaFuncSetAttribute(k_gemm<128, true,  false>, cudaFuncAttributeMaxDynamicSharedMemorySize, SMEM128);

    // preprocessing (5 launches so ncu -s 5 lands on k_aggx)
    k_detect_init<<<196, 256>>>((const int*)ei);
    k_prep_edges<<<2500, 256>>>(ei);
    k_finish_dinv<<<196, 256>>>();
    k_scan<<<1, 1024>>>();
    k_csr_fill<<<2500, 256>>>();

    // layer 0: aggregate raw x (64-wide), then GEMM with bias+relu epilogue -> h in d_agg
    k_aggx<<<6250, 256>>>(x);
    k_gemm<64, false, true><<<782, 256, SMEM64>>>((const float*)p_aggx, W0, b0, (float*)p_agg);

    // layers 1..4 (GCN + BN, BN applied lazily in next GEMM's input load)
    for (int i = 0; i < GD_; i++) {
        if (i == 0)
            k_gemm<128, false, false><<<782, 256, SMEM128>>>((const float*)p_agg, Wg, nullptr, (float*)p_hw);
        else
            k_gemm<128, true, false><<<782, 256, SMEM128>>>((const float*)p_agg,
                                                            Wg + (size_t)i * 128 * 128, nullptr, (float*)p_hw);
        cudaMemsetAsync(p_stats, 0, 2 * 128 * sizeof(float));
        k_agg<<<782, 256>>>(bg + (size_t)i * 128);
        k_bn_params<<<1, 128>>>(gamma_g + (size_t)i * 128, beta_g + (size_t)i * 128);
    }

    // fused BN-apply + pooling
    cudaMemsetAsync(p_hp, 0, (size_t)GG * 128 * sizeof(float));
    k_bnpool<<<6250, 256>>>(batch);

    // head
    k_head0<<<128, 256>>>(Wl0, bl0);
    for (int i = 0; i < LD_; i++) {
        k_headgemm<<<128, 256>>>(Wl + (size_t)i * 256 * 256, bl + (size_t)i * 256);
        k_lbn_stats<<<256, 256>>>(gamma_l + (size_t)i * 256, beta_l + (size_t)i * 256);
        k_lbn_apply<<<1024, 256>>>();
    }
    k_final<<<1024, 64>>>(Wout, bout, (float*)d_out);
}

// round 8
// speedup vs baseline: 1.0642x; 1.0642x over previous
#include <cuda_runtime.h>

// Problem constants (fixed shapes)
#define NN   50000
#define EE   640000
#define DIN  64
#define GB_  128
#define GD_  4
#define LB_  256
#define LD_  2
#define GG   1024
#define NBLK 196          // scan blocks: 196*256 >= NN

typedef unsigned long long ull;

// ---------------- device scratch ----------------
__device__ __align__(16) float d_dinv[NN];
__device__ int   d_ideg[NN];
__device__ int   d_off[NN + 1];
__device__ int   d_cursor[NN];
__device__ int   d_bsum[NBLK];
__device__ int   d_srcA[EE];
__device__ int   d_dstA[EE];
__device__ __align__(16) int2  d_csr[EE];      // {src, float_bits(enorm)}
__device__ __align__(16) float d_aggx[(size_t)NN * DIN];
__device__ __align__(16) float d_hw [(size_t)NN * GB_];
__device__ __align__(16) float d_agg[(size_t)NN * GB_];
__device__ __align__(16) float d_stats[2 * GB_];
__device__ __align__(16) float d_scale[GB_];
__device__ __align__(16) float d_shift[GB_];
__device__ __align__(16) float d_hp[GG * GB_];
__device__ __align__(16) float d_l0[GG * LB_];
__device__ __align__(16) float d_l1[GG * LB_];
__device__ __align__(16) float d_lscale[LB_];
__device__ __align__(16) float d_lshift[LB_];
__device__ int d_is64;

// ---------------- helpers ----------------
__device__ __forceinline__ void red_add_v4(float* p, float a, float b, float c, float d) {
    asm volatile("red.global.add.v4.f32 [%0], {%1, %2, %3, %4};"
                 :: "l"(p), "f"(a), "f"(b), "f"(c), "f"(d) : "memory");
}
__device__ __forceinline__ ull ffma2(ull a, ull b, ull c) {
    ull r;
    asm("fma.rn.f32x2 %0, %1, %2, %3;" : "=l"(r) : "l"(a), "l"(b), "l"(c));
    return r;
}
__device__ __forceinline__ float2 unpack2(ull v) {
    float2 r;
    asm("mov.b64 {%0, %1}, %2;" : "=f"(r.x), "=f"(r.y) : "l"(v));
    return r;
}

// ---------------- preprocessing ----------------
__global__ void k_detect_init(const int* __restrict__ ei32) {
    int n = blockIdx.x * blockDim.x + threadIdx.x;
    if (n < NN) d_ideg[n] = 0;
    if (blockIdx.x == 0 && threadIdx.x == 0) {
        int zeros = 0;
        for (int i = 0; i < 64; i++)
            if (ei32[2 * i + 1] == 0) zeros++;
        d_is64 = (zeros >= 60) ? 1 : 0;
    }
}

__global__ void k_prep_edges(const void* __restrict__ ei) {
    int e = blockIdx.x * blockDim.x + threadIdx.x;
    if (e < EE) {
        int s, d;
        if (d_is64) {
            const long long* p = (const long long*)ei;
            s = (int)p[e];
            d = (int)p[EE + e];
        } else {
            const int* p = (const int*)ei;
            s = p[e];
            d = p[EE + e];
        }
        s = min(max(s, 0), NN - 1);
        d = min(max(d, 0), NN - 1);
        d_srcA[e] = s;
        d_dstA[e] = d;
        atomicAdd(&d_ideg[d], 1);
    }
}

// scan pass 1: per-block exclusive scan of ideg -> d_off (local), block totals -> d_bsum.
// also computes dinv (deg -> rsqrt) in the same pass.
__global__ __launch_bounds__(256) void k_scan1() {
    __shared__ int wsum[8];
    int t = threadIdx.x, lane = t & 31, wid = t >> 5;
    int n = blockIdx.x * 256 + t;
    int v = (n < NN) ? d_ideg[n] : 0;
    if (n < NN) d_dinv[n] = rsqrtf((float)(1 + v));
    int x = v;
    #pragma unroll
    for (int o = 1; o < 32; o <<= 1) {
        int y = __shfl_up_sync(0xffffffffu, x, o);
        if (lane >= o) x += y;
    }
    if (lane == 31) wsum[wid] = x;
    __syncthreads();
    if (wid == 0 && lane < 8) {
        int y = wsum[lane];
        #pragma unroll
        for (int o = 1; o < 8; o <<= 1) {
            int z = __shfl_up_sync(0xffu, y, o);
            if (lane >= o) y += z;
        }
        wsum[lane] = y;
    }
    __syncthreads();
    int excl = (wid > 0 ? wsum[wid - 1] : 0) + x - v;
    if (n < NN) d_off[n] = excl;
    if (t == 255) d_bsum[blockIdx.x] = wsum[7];
}

// scan pass 2: exclusive scan of the NBLK block sums (single block)
__global__ __launch_bounds__(256) void k_scan2() {
    __shared__ int wsum[8];
    int t = threadIdx.x, lane = t & 31, wid = t >> 5;
    int v = (t < NBLK) ? d_bsum[t] : 0;
    int x = v;
    #pragma unroll
    for (int o = 1; o < 32; o <<= 1) {
        int y = __shfl_up_sync(0xffffffffu, x, o);
        if (lane >= o) x += y;
    }
    if (lane == 31) wsum[wid] = x;
    __syncthreads();
    if (wid == 0 && lane < 8) {
        int y = wsum[lane];
        #pragma unroll
        for (int o = 1; o < 8; o <<= 1) {
            int z = __shfl_up_sync(0xffu, y, o);
            if (lane >= o) y += z;
        }
        wsum[lane] = y;
    }
    __syncthreads();
    int excl = (wid > 0 ? wsum[wid - 1] : 0) + x - v;
    if (t < NBLK) d_bsum[t] = excl;
    if (t == 0) d_off[NN] = EE;   // total degree is exactly E
}

// scan pass 3: add block offsets, init cursor
__global__ void k_scan3() {
    int n = blockIdx.x * 256 + threadIdx.x;
    if (n < NN) {
        int o = d_off[n] + d_bsum[blockIdx.x];
        d_off[n] = o;
        d_cursor[n] = o;
    }
}

__global__ void k_csr_fill() {
    int e = blockIdx.x * blockDim.x + threadIdx.x;
    if (e < EE) {
        int s = d_srcA[e], d = d_dstA[e];
        int pos = atomicAdd(&d_cursor[d], 1);
        float w = d_dinv[s] * d_dinv[d];
        d_csr[pos] = make_int2(s, __float_as_int(w));
    }
}

// ---------------- layer-0 aggregation on raw x (64 wide) ----------------
__global__ __launch_bounds__(256) void k_aggx(const float* __restrict__ x) {
    int n = blockIdx.x * 8 + (threadIdx.x >> 5);
    if (n >= NN) return;
    int lane = threadIdx.x & 31;
    float sn = __ldg(&d_dinv[n]);
    float sn2 = sn * sn;
    float2 vs = __ldg((const float2*)(x + (size_t)n * DIN) + lane);
    float2 acc = make_float2(vs.x * sn2, vs.y * sn2);

    int o0 = __ldg(&d_off[n]), o1 = __ldg(&d_off[n + 1]);
    int2 e0 = make_int2(0, 0), e1 = make_int2(0, 0);
    if (o0 < o1)     e0 = __ldg(&d_csr[o0]);
    if (o0 + 1 < o1) e1 = __ldg(&d_csr[o0 + 1]);
    for (int e = o0; e < o1; e++) {
        int2 e2 = make_int2(0, 0);
        if (e + 2 < o1) e2 = __ldg(&d_csr[e + 2]);
        float w = __int_as_float(e0.y);
        float2 v = __ldg((const float2*)(x + (size_t)e0.x * DIN) + lane);
        acc.x += v.x * w; acc.y += v.y * w;
        e0 = e1; e1 = e2;
    }
    *((float2*)(d_aggx + (size_t)n * DIN) + lane) = acc;
}

// ---------------- node GEMM: out[N,128] = f(in)[N,K] @ W[K,128] ----------------
// 32 rows per block. Weights natural layout (adjacent-pair LDS.64).
// h stored duplicated (h,h) transposed: hs[k][2*r] -- broadcast LDS.64 reads.
// Smem: K*128*4 (ws) + K*64*4 (hs) = 96KB (K=128) / 48KB (K=64) -> 2 CTAs/SM.
// INBN: apply scale/shift+relu to input while loading. EPI: bias + relu on output.
template <int K, bool INBN, bool EPI>
__global__ __launch_bounds__(256) void k_gemm(const float* __restrict__ h,
                                              const float* __restrict__ W,
                                              const float* __restrict__ bias,
                                              float* __restrict__ out) {
    extern __shared__ float sm[];
    float* ws = sm;            // [K][128]
    float* hs = sm + K * 128;  // [K][64]  (32 rows duplicated as pairs)
    int t = threadIdx.x;
    int row0 = blockIdx.x * 32;

    for (int i = t; i < K * 32; i += 256)
        ((float4*)ws)[i] = ((const float4*)W)[i];

    // h tile: load float4 (4 k's of one row), store duplicated transposed
    for (int i = t; i < 32 * (K / 4); i += 256) {
        int row = i & 31;
        int kq = i >> 5;
        int grow = row0 + row;
        if (grow < NN) {
            float4 v = *(const float4*)(h + (size_t)grow * K + 4 * kq);
            if (INBN) {
                float4 sc = *(const float4*)&d_scale[4 * kq];
                float4 sh = *(const float4*)&d_shift[4 * kq];
                v.x = fmaxf(v.x * sc.x + sh.x, 0.0f);
                v.y = fmaxf(v.y * sc.y + sh.y, 0.0f);
                v.z = fmaxf(v.z * sc.z + sh.z, 0.0f);
                v.w = fmaxf(v.w * sc.w + sh.w, 0.0f);
            }
            *(float2*)&hs[(4 * kq + 0) * 64 + 2 * row] = make_float2(v.x, v.x);
            *(float2*)&hs[(4 * kq + 1) * 64 + 2 * row] = make_float2(v.y, v.y);
            *(float2*)&hs[(4 * kq + 2) * 64 + 2 * row] = make_float2(v.z, v.z);
            *(float2*)&hs[(4 * kq + 3) * 64 + 2 * row] = make_float2(v.w, v.w);
        } else {
            *(float2*)&hs[(4 * kq + 0) * 64 + 2 * row] = make_float2(0.f, 0.f);
            *(float2*)&hs[(4 * kq + 1) * 64 + 2 * row] = make_float2(0.f, 0.f);
            *(float2*)&hs[(4 * kq + 2) * 64 + 2 * row] = make_float2(0.f, 0.f);
            *(float2*)&hs[(4 * kq + 3) * 64 + 2 * row] = make_float2(0.f, 0.f);
        }
    }
    __syncthreads();

    int warp = t >> 5, lane = t & 31;
    int wr0 = warp * 4;            // 4 rows per warp
    // acc[j][c]: row wr0+j, col pair (2lane, 2lane+1) for c=0; (64+2lane, 64+2lane+1) for c=1
    ull acc[4][2] = {};
    #pragma unroll 4
    for (int k = 0; k < K; k++) {
        ull wa = *(const ull*)&ws[k * 128 + 2 * lane];
        ull wb = *(const ull*)&ws[k * 128 + 64 + 2 * lane];
        ull h0 = *(const ull*)&hs[k * 64 + 2 * wr0];
        ull h1 = *(const ull*)&hs[k * 64 + 2 * wr0 + 2];
        ull h2 = *(const ull*)&hs[k * 64 + 2 * wr0 + 4];
        ull h3 = *(const ull*)&hs[k * 64 + 2 * wr0 + 6];
        acc[0][0] = ffma2(h0, wa, acc[0][0]); acc[0][1] = ffma2(h0, wb, acc[0][1]);
        acc[1][0] = ffma2(h1, wa, acc[1][0]); acc[1][1] = ffma2(h1, wb, acc[1][1]);
        acc[2][0] = ffma2(h2, wa, acc[2][0]); acc[2][1] = ffma2(h2, wb, acc[2][1]);
        acc[3][0] = ffma2(h3, wa, acc[3][0]); acc[3][1] = ffma2(h3, wb, acc[3][1]);
    }

    float2 bb0, bb1;
    if (EPI) {
        bb0 = *(const float2*)&bias[2 * lane];
        bb1 = *(const float2*)&bias[64 + 2 * lane];
    }
    #pragma unroll
    for (int j = 0; j < 4; j++) {
        int r = row0 + wr0 + j;
        if (r < NN) {
            float2 v0 = unpack2(acc[j][0]);
            float2 v1 = unpack2(acc[j][1]);
            if (EPI) {
                v0.x = fmaxf(v0.x + bb0.x, 0.0f); v0.y = fmaxf(v0.y + bb0.y, 0.0f);
                v1.x = fmaxf(v1.x + bb1.x, 0.0f); v1.y = fmaxf(v1.y + bb1.y, 0.0f);
            }
            float* o = out + (size_t)r * 128;
            *(float2*)(o + 2 * lane)      = v0;
            *(float2*)(o + 64 + 2 * lane) = v1;
        }
    }
}

// ---------------- CSR aggregation (128-wide) + BN stats ----------------
__global__ __launch_bounds__(256) void k_agg(const float* __restrict__ bias) {
    __shared__ float ss[128], sq[128];
    int t = threadIdx.x, lane = t & 31, warp = t >> 5;
    if (t < 128) { ss[t] = 0.f; sq[t] = 0.f; }
    __syncthreads();
    float4 bias4 = __ldg((const float4*)bias + lane);
    float4 sum4 = {0, 0, 0, 0}, sq4 = {0, 0, 0, 0};

    int n0 = (blockIdx.x * 8 + warp) * 8;
    for (int j = 0; j < 8; j++) {
        int n = n0 + j;
        if (n >= NN) break;
        float4 acc = bias4;
        int o0 = __ldg(&d_off[n]), o1 = __ldg(&d_off[n + 1]);
        int2 e0 = make_int2(0, 0), e1 = make_int2(0, 0);
        if (o0 < o1)     e0 = __ldg(&d_csr[o0]);
        if (o0 + 1 < o1) e1 = __ldg(&d_csr[o0 + 1]);
        for (int e = o0; e < o1; e++) {
            int2 e2 = make_int2(0, 0);
            if (e + 2 < o1) e2 = __ldg(&d_csr[e + 2]);
            float w = __int_as_float(e0.y);
            float4 v = __ldg((const float4*)(d_hw + (size_t)e0.x * 128) + lane);
            acc.x += v.x * w; acc.y += v.y * w; acc.z += v.z * w; acc.w += v.w * w;
            e0 = e1; e1 = e2;
        }
        float sn = __ldg(&d_dinv[n]);
        float sn2 = sn * sn;
        float4 vs = *((const float4*)(d_hw + (size_t)n * 128) + lane);
        acc.x += vs.x * sn2; acc.y += vs.y * sn2; acc.z += vs.z * sn2; acc.w += vs.w * sn2;

        *((float4*)(d_agg + (size_t)n * 128) + lane) = acc;
        sum4.x += acc.x; sum4.y += acc.y; sum4.z += acc.z; sum4.w += acc.w;
        sq4.x += acc.x * acc.x; sq4.y += acc.y * acc.y;
        sq4.z += acc.z * acc.z; sq4.w += acc.w * acc.w;
    }
    int c = lane * 4;
    atomicAdd(&ss[c + 0], sum4.x); atomicAdd(&ss[c + 1], sum4.y);
    atomicAdd(&ss[c + 2], sum4.z); atomicAdd(&ss[c + 3], sum4.w);
    atomicAdd(&sq[c + 0], sq4.x);  atomicAdd(&sq[c + 1], sq4.y);
    atomicAdd(&sq[c + 2], sq4.z);  atomicAdd(&sq[c + 3], sq4.w);
    __syncthreads();
    if (t < 128) {
        atomicAdd(&d_stats[t], ss[t]);
        atomicAdd(&d_stats[128 + t], sq[t]);
    }
}

__global__ void k_bn_params(const float* __restrict__ gamma, const float* __restrict__ beta) {
    int c = threadIdx.x;  // 128 threads
    float m = d_stats[c] * (1.0f / NN);
    float v = d_stats[128 + c] * (1.0f / NN) - m * m;
    float sc = gamma[c] * rsqrtf(v + 1e-5f);
    d_scale[c] = sc;
    d_shift[c] = beta[c] - m * sc;
}

// ---------------- fused BN-apply + pooling (final GCN layer) ----------------
__global__ __launch_bounds__(256) void k_bnpool(const void* __restrict__ batch) {
    int n = blockIdx.x * 8 + (threadIdx.x >> 5);
    if (n >= NN) return;
    int lane = threadIdx.x & 31;
    int g;
    if (d_is64) g = (int)((const long long*)batch)[n];
    else        g = ((const int*)batch)[n];
    g = min(max(g, 0), GG - 1);
    int c = lane * 4;
    float4 sc = *(const float4*)&d_scale[c];
    float4 sh = *(const float4*)&d_shift[c];
    float4 v = *((const float4*)(d_agg + (size_t)n * 128) + lane);
    v.x = fmaxf(v.x * sc.x + sh.x, 0.f);
    v.y = fmaxf(v.y * sc.y + sh.y, 0.f);
    v.z = fmaxf(v.z * sc.z + sh.z, 0.f);
    v.w = fmaxf(v.w * sc.w + sh.w, 0.f);
    red_add_v4(d_hp + (size_t)g * 128 + c, v.x, v.y, v.z, v.w);
}

// ---------------- head layer 0: l0 = relu(hp @ Wl0 + bl0) ----------------
__global__ __launch_bounds__(256) void k_head0(const float* __restrict__ W, const float* __restrict__ b) {
    __shared__ float in_s[8 * 128];
    int t = threadIdx.x;
    int g0 = blockIdx.x * 8;
    for (int i = t; i < (8 * 128) / 4; i += 256)
        ((float4*)in_s)[i] = ((const float4*)(d_hp + (size_t)g0 * 128))[i];
    __syncthreads();
    float acc[8] = {};
    for (int k = 0; k < 128; k++) {
        float w = W[k * 256 + t];
        #pragma unroll
        for (int r = 0; r < 8; r++) acc[r] += in_s[r * 128 + k] * w;
    }
    float bb = b[t];
    #pragma unroll
    for (int r = 0; r < 8; r++)
        d_l0[(size_t)(g0 + r) * 256 + t] = fmaxf(acc[r] + bb, 0.0f);
}

// ---------------- head GEMM: l1 = l0 @ W + b ----------------
__global__ __launch_bounds__(256) void k_headgemm(const float* __restrict__ W, const float* __restrict__ b) {
    __shared__ float in_s[8 * 256];
    int t = threadIdx.x;
    int g0 = blockIdx.x * 8;
    for (int i = t; i < (8 * 256) / 4; i += 256)
        ((float4*)in_s)[i] = ((const float4*)(d_l0 + (size_t)g0 * 256))[i];
    __syncthreads();
    float acc[8] = {};
    for (int k = 0; k < 256; k++) {
        float w = W[k * 256 + t];
        #pragma unroll
        for (int r = 0; r < 8; r++) acc[r] += in_s[r * 256 + k] * w;
    }
    float bb = b[t];
    #pragma unroll
    for (int r = 0; r < 8; r++)
        d_l1[(size_t)(g0 + r) * 256 + t] = acc[r] + bb;
}

// ---------------- head BN ----------------
__global__ __launch_bounds__(256) void k_lbn_stats(const float* __restrict__ gamma, const float* __restrict__ beta) {
    int c = blockIdx.x;
    int t = threadIdx.x;
    float ls = 0.f, lss = 0.f;
    for (int r = t; r < GG; r += 256) {
        float v = d_l1[(size_t)r * 256 + c];
        ls += v; lss += v * v;
    }
    __shared__ float ss[256], sq[256];
    ss[t] = ls; sq[t] = lss;
    __syncthreads();
    for (int o = 128; o > 0; o >>= 1) {
        if (t < o) { ss[t] += ss[t + o]; sq[t] += sq[t + o]; }
        __syncthreads();
    }
    if (t == 0) {
        float m = ss[0] * (1.0f / GG);
        float v = sq[0] * (1.0f / GG) - m * m;
        float sc = gamma[c] * rsqrtf(v + 1e-5f);
        d_lscale[c] = sc;
        d_lshift[c] = beta[c] - m * sc;
    }
}

__global__ void k_lbn_apply() {
    size_t idx = (size_t)blockIdx.x * 256 + threadIdx.x;
    if (idx < (size_t)GG * 256) {
        int c = (int)(idx & 255);
        d_l0[idx] = fmaxf(d_l1[idx] * d_lscale[c] + d_lshift[c], 0.0f);
    }
}

// ---------------- final: out = l0 @ Wout + bout ----------------
__global__ __launch_bounds__(64) void k_final(const float* __restrict__ Wout,
                                              const float* __restrict__ bout,
                                              float* __restrict__ out) {
    int r = blockIdx.x;
    int warp = threadIdx.x >> 5;
    int lane = threadIdx.x & 31;
    float s = 0.f;
    for (int k = lane; k < 256; k += 32)
        s += d_l0[(size_t)r * 256 + k] * Wout[k * 2 + warp];
    #pragma unroll
    for (int o = 16; o > 0; o >>= 1) s += __shfl_down_sync(0xffffffffu, s, o);
    if (lane == 0) out[r * 2 + warp] = s + bout[warp];
}

// ---------------- launch ----------------
extern "C" void kernel_launch(void* const* d_in, const int* in_sizes, int n_in,
                              void* d_out, int out_size) {
    const float* x     = (const float*)d_in[0];
    const void*  ei    = d_in[1];
    const void*  batch = d_in[2];
    int base = (n_in >= 18) ? 4 : 3;
    const float* W0      = (const float*)d_in[base + 0];
    const float* b0      = (const float*)d_in[base + 1];
    const float* Wg      = (const float*)d_in[base + 2];
    const float* bg      = (const float*)d_in[base + 3];
    const float* gamma_g = (const float*)d_in[base + 4];
    const float* beta_g  = (const float*)d_in[base + 5];
    const float* Wl0     = (const float*)d_in[base + 6];
    const float* bl0     = (const float*)d_in[base + 7];
    const float* Wl      = (const float*)d_in[base + 8];
    const float* bl      = (const float*)d_in[base + 9];
    const float* gamma_l = (const float*)d_in[base + 10];
    const float* beta_l  = (const float*)d_in[base + 11];
    const float* Wout    = (const float*)d_in[base + 12];
    const float* bout    = (const float*)d_in[base + 13];

    void *p_stats, *p_hp, *p_agg, *p_hw, *p_aggx;
    cudaGetSymbolAddress(&p_stats, d_stats);
    cudaGetSymbolAddress(&p_hp, d_hp);
    cudaGetSymbolAddress(&p_agg, d_agg);
    cudaGetSymbolAddress(&p_hw, d_hw);
    cudaGetSymbolAddress(&p_aggx, d_aggx);

    const int SMEM64  = (64 * 128 + 64 * 64) * 4;     // 48 KB
    const int SMEM128 = (128 * 128 + 128 * 64) * 4;   // 96 KB -> 2 CTAs/SM
    cudaFuncSetAttribute(k_gemm<64,  false, true>,  cudaFuncAttributeMaxDynamicSharedMemorySize, SMEM64);
    cudaFuncSetAttribute(k_gemm<128, false, false>, cudaFuncAttributeMaxDynamicSharedMemorySize, SMEM128);
    cudaFuncSetAttribute(k_gemm<128, true,  false>, cudaFuncAttributeMaxDynamicSharedMemorySize, SMEM128);

    const int GEMM_GRID = (NN + 31) / 32;   // 1563

    // preprocessing
    k_detect_init<<<NBLK, 256>>>((const int*)ei);
    k_prep_edges<<<2500, 256>>>(ei);
    k_scan1<<<NBLK, 256>>>();
    k_scan2<<<1, 256>>>();
    k_scan3<<<NBLK, 256>>>();
    k_csr_fill<<<2500, 256>>>();

    // layer 0: aggregate raw x (64-wide), GEMM with bias+relu epilogue -> h in d_agg
    k_aggx<<<6250, 256>>>(x);
    k_gemm<64, false, true><<<GEMM_GRID, 256, SMEM64>>>((const float*)p_aggx, W0, b0, (float*)p_agg);

    // layers 1..4 (GCN + BN, BN applied lazily in next GEMM's input load)
    for (int i = 0; i < GD_; i++) {
        if (i == 0)
            k_gemm<128, false, false><<<GEMM_GRID, 256, SMEM128>>>((const float*)p_agg, Wg, nullptr, (float*)p_hw);
        else
            k_gemm<128, true, false><<<GEMM_GRID, 256, SMEM128>>>((const float*)p_agg,
                                                                  Wg + (size_t)i * 128 * 128, nullptr, (float*)p_hw);
        cudaMemsetAsync(p_stats, 0, 2 * 128 * sizeof(float));
        k_agg<<<782, 256>>>(bg + (size_t)i * 128);
        k_bn_params<<<1, 128>>>(gamma_g + (size_t)i * 128, beta_g + (size_t)i * 128);
    }

    // fused BN-apply + pooling
    cudaMemsetAsync(p_hp, 0, (size_t)GG * 128 * sizeof(float));
    k_bnpool<<<6250, 256>>>(batch);

    // head
    k_head0<<<128, 256>>>(Wl0, bl0);
    for (int i = 0; i < LD_; i++) {
        k_headgemm<<<128, 256>>>(Wl + (size_t)i * 256 * 256, bl + (size_t)i * 256);
        k_lbn_stats<<<256, 256>>>(gamma_l + (size_t)i * 256, beta_l + (size_t)i * 256);
        k_lbn_apply<<<1024, 256>>>();
    }
    k_final<<<1024, 64>>>(Wout, bout, (float*)d_out);
}

// round 9
// speedup vs baseline: 1.2776x; 1.2005x over previous
#include <cuda_runtime.h>

// Problem constants (fixed shapes)
#define NN   50000
#define EE   640000
#define DIN  64
#define GB_  128
#define GD_  4
#define LB_  256
#define LD_  2
#define GG   1024
#define NBLK 196          // scan blocks: 196*256 >= NN

typedef unsigned long long ull;

// ---------------- device scratch ----------------
__device__ __align__(16) float d_dinv[NN];
__device__ int   d_ideg[NN];
__device__ int   d_off[NN + 1];
__device__ int   d_cursor[NN];
__device__ int   d_bsum[NBLK];
__device__ int   d_srcA[EE];
__device__ int   d_dstA[EE];
__device__ __align__(16) int2  d_csr[EE];      // {src, float_bits(enorm)}
__device__ __align__(16) float d_aggx[(size_t)NN * DIN];
__device__ __align__(16) float d_hw [(size_t)NN * GB_];
__device__ __align__(16) float d_agg[(size_t)NN * GB_];
__device__ __align__(16) float d_stats[2 * GB_];
__device__ __align__(16) float d_scale[GB_];
__device__ __align__(16) float d_shift[GB_];
__device__ __align__(16) float d_hp[GG * GB_];
__device__ __align__(16) float d_l0[GG * LB_];
__device__ __align__(16) float d_l1[GG * LB_];
__device__ __align__(16) float d_lscale[LB_];
__device__ __align__(16) float d_lshift[LB_];
__device__ int d_is64;

// ---------------- helpers ----------------
__device__ __forceinline__ void red_add_v4(float* p, float a, float b, float c, float d) {
    asm volatile("red.global.add.v4.f32 [%0], {%1, %2, %3, %4};"
                 :: "l"(p), "f"(a), "f"(b), "f"(c), "f"(d) : "memory");
}
__device__ __forceinline__ ull ffma2(ull a, ull b, ull c) {
    ull r;
    asm("fma.rn.f32x2 %0, %1, %2, %3;" : "=l"(r) : "l"(a), "l"(b), "l"(c));
    return r;
}
__device__ __forceinline__ float2 unpack2(ull v) {
    float2 r;
    asm("mov.b64 {%0, %1}, %2;" : "=f"(r.x), "=f"(r.y) : "l"(v));
    return r;
}

// ---------------- preprocessing ----------------
__global__ void k_detect_init(const int* __restrict__ ei32) {
    int n = blockIdx.x * blockDim.x + threadIdx.x;
    if (n < NN) d_ideg[n] = 0;
    if (blockIdx.x == 0 && threadIdx.x == 0) {
        int zeros = 0;
        for (int i = 0; i < 64; i++)
            if (ei32[2 * i + 1] == 0) zeros++;
        d_is64 = (zeros >= 60) ? 1 : 0;
    }
}

__global__ void k_prep_edges(const void* __restrict__ ei) {
    int e = blockIdx.x * blockDim.x + threadIdx.x;
    if (e < EE) {
        int s, d;
        if (d_is64) {
            const long long* p = (const long long*)ei;
            s = (int)p[e];
            d = (int)p[EE + e];
        } else {
            const int* p = (const int*)ei;
            s = p[e];
            d = p[EE + e];
        }
        s = min(max(s, 0), NN - 1);
        d = min(max(d, 0), NN - 1);
        d_srcA[e] = s;
        d_dstA[e] = d;
        atomicAdd(&d_ideg[d], 1);
    }
}

// scan pass 1: per-block exclusive scan of ideg -> d_off (local), block totals -> d_bsum.
__global__ __launch_bounds__(256) void k_scan1() {
    __shared__ int wsum[8];
    int t = threadIdx.x, lane = t & 31, wid = t >> 5;
    int n = blockIdx.x * 256 + t;
    int v = (n < NN) ? d_ideg[n] : 0;
    if (n < NN) d_dinv[n] = rsqrtf((float)(1 + v));
    int x = v;
    #pragma unroll
    for (int o = 1; o < 32; o <<= 1) {
        int y = __shfl_up_sync(0xffffffffu, x, o);
        if (lane >= o) x += y;
    }
    if (lane == 31) wsum[wid] = x;
    __syncthreads();
    if (wid == 0 && lane < 8) {
        int y = wsum[lane];
        #pragma unroll
        for (int o = 1; o < 8; o <<= 1) {
            int z = __shfl_up_sync(0xffu, y, o);
            if (lane >= o) y += z;
        }
        wsum[lane] = y;
    }
    __syncthreads();
    int excl = (wid > 0 ? wsum[wid - 1] : 0) + x - v;
    if (n < NN) d_off[n] = excl;
    if (t == 255) d_bsum[blockIdx.x] = wsum[7];
}

// scan pass 2: exclusive scan of the NBLK block sums (single block)
__global__ __launch_bounds__(256) void k_scan2() {
    __shared__ int wsum[8];
    int t = threadIdx.x, lane = t & 31, wid = t >> 5;
    int v = (t < NBLK) ? d_bsum[t] : 0;
    int x = v;
    #pragma unroll
    for (int o = 1; o < 32; o <<= 1) {
        int y = __shfl_up_sync(0xffffffffu, x, o);
        if (lane >= o) x += y;
    }
    if (lane == 31) wsum[wid] = x;
    __syncthreads();
    if (wid == 0 && lane < 8) {
        int y = wsum[lane];
        #pragma unroll
        for (int o = 1; o < 8; o <<= 1) {
            int z = __shfl_up_sync(0xffu, y, o);
            if (lane >= o) y += z;
        }
        wsum[lane] = y;
    }
    __syncthreads();
    int excl = (wid > 0 ? wsum[wid - 1] : 0) + x - v;
    if (t < NBLK) d_bsum[t] = excl;
    if (t == 0) d_off[NN] = EE;
}

// scan pass 3: add block offsets, init cursor
__global__ void k_scan3() {
    int n = blockIdx.x * 256 + threadIdx.x;
    if (n < NN) {
        int o = d_off[n] + d_bsum[blockIdx.x];
        d_off[n] = o;
        d_cursor[n] = o;
    }
}

__global__ void k_csr_fill() {
    int e = blockIdx.x * blockDim.x + threadIdx.x;
    if (e < EE) {
        int s = d_srcA[e], d = d_dstA[e];
        int pos = atomicAdd(&d_cursor[d], 1);
        float w = d_dinv[s] * d_dinv[d];
        d_csr[pos] = make_int2(s, __float_as_int(w));
    }
}

// ---------------- layer-0 aggregation on raw x (64 wide) ----------------
__global__ __launch_bounds__(256) void k_aggx(const float* __restrict__ x) {
    int n = blockIdx.x * 8 + (threadIdx.x >> 5);
    if (n >= NN) return;
    int lane = threadIdx.x & 31;
    float sn = __ldg(&d_dinv[n]);
    float sn2 = sn * sn;
    float2 vs = __ldg((const float2*)(x + (size_t)n * DIN) + lane);
    float2 acc = make_float2(vs.x * sn2, vs.y * sn2);

    int o0 = __ldg(&d_off[n]), o1 = __ldg(&d_off[n + 1]);
    int2 e0 = make_int2(0, 0), e1 = make_int2(0, 0);
    if (o0 < o1)     e0 = __ldg(&d_csr[o0]);
    if (o0 + 1 < o1) e1 = __ldg(&d_csr[o0 + 1]);
    for (int e = o0; e < o1; e++) {
        int2 e2 = make_int2(0, 0);
        if (e + 2 < o1) e2 = __ldg(&d_csr[e + 2]);
        float w = __int_as_float(e0.y);
        float2 v = __ldg((const float2*)(x + (size_t)e0.x * DIN) + lane);
        acc.x += v.x * w; acc.y += v.y * w;
        e0 = e1; e1 = e2;
    }
    *((float2*)(d_aggx + (size_t)n * DIN) + lane) = acc;
}

// ---------------- node GEMM: out[N,128] = f(in)[N,K] @ W[K,128] ----------------
// 64 rows/block, K tiled in 64-chunks. Smem 64KB -> 3 CTAs/SM.
//   ws: [64][128] natural weights (adjacent-pair LDS.64, conflict-free)
//   hs: [64][128] h duplicated pairs, transposed: hs[kk][2r] = (h[r][kc+kk], same)
// Inner loop per k: 2 LDS.64 (weights) + 8 broadcast LDS.64 (h) + 16 FFMA2. No packing MOVs.
template <int K, bool INBN, bool EPI>
__global__ __launch_bounds__(256) void k_gemm(const float* __restrict__ h,
                                              const float* __restrict__ W,
                                              const float* __restrict__ bias,
                                              float* __restrict__ out) {
    extern __shared__ float sm[];
    float* ws = sm;           // [64][128]
    float* hs = sm + 64 * 128; // [64][128] duplicated
    int t = threadIdx.x;
    int row0 = blockIdx.x * 64;
    int warp = t >> 5, lane = t & 31;
    int wr0 = warp * 8;

    ull acc[8][2] = {};

    #pragma unroll
    for (int kc = 0; kc < K; kc += 64) {
        if (kc > 0) __syncthreads();
        // weights rows kc..kc+63 (float4 vectorized)
        for (int i = t; i < 64 * 32; i += 256)
            ((float4*)ws)[i] = ((const float4*)(W + (size_t)kc * 128))[i];
        // h tile chunk: rows row0..row0+63, k cols kc..kc+63, duplicated transposed.
        // i -> (q = i>>6 in [0,16), row = i&63): lanes cover consecutive rows.
        for (int i = t; i < 64 * 16; i += 256) {
            int row = i & 63;
            int q = i >> 6;
            int grow = row0 + row;
            float4 v = make_float4(0.f, 0.f, 0.f, 0.f);
            if (grow < NN) {
                v = *(const float4*)(h + (size_t)grow * K + kc + 4 * q);
                if (INBN) {
                    float4 sc = *(const float4*)&d_scale[kc + 4 * q];
                    float4 sh = *(const float4*)&d_shift[kc + 4 * q];
                    v.x = fmaxf(v.x * sc.x + sh.x, 0.0f);
                    v.y = fmaxf(v.y * sc.y + sh.y, 0.0f);
                    v.z = fmaxf(v.z * sc.z + sh.z, 0.0f);
                    v.w = fmaxf(v.w * sc.w + sh.w, 0.0f);
                }
            }
            *(float2*)&hs[(4 * q + 0) * 128 + 2 * row] = make_float2(v.x, v.x);
            *(float2*)&hs[(4 * q + 1) * 128 + 2 * row] = make_float2(v.y, v.y);
            *(float2*)&hs[(4 * q + 2) * 128 + 2 * row] = make_float2(v.z, v.z);
            *(float2*)&hs[(4 * q + 3) * 128 + 2 * row] = make_float2(v.w, v.w);
        }
        __syncthreads();

        #pragma unroll 2
        for (int kk = 0; kk < 64; kk++) {
            ull wa = *(const ull*)&ws[kk * 128 + 2 * lane];
            ull wb = *(const ull*)&ws[kk * 128 + 64 + 2 * lane];
            #pragma unroll
            for (int r = 0; r < 8; r++) {
                ull hv = *(const ull*)&hs[kk * 128 + 2 * (wr0 + r)];  // broadcast
                acc[r][0] = ffma2(hv, wa, acc[r][0]);
                acc[r][1] = ffma2(hv, wb, acc[r][1]);
            }
        }
    }

    float2 bb0, bb1;
    if (EPI) {
        bb0 = *(const float2*)&bias[2 * lane];
        bb1 = *(const float2*)&bias[64 + 2 * lane];
    }
    #pragma unroll
    for (int r = 0; r < 8; r++) {
        int grow = row0 + wr0 + r;
        if (grow < NN) {
            float2 v0 = unpack2(acc[r][0]);
            float2 v1 = unpack2(acc[r][1]);
            if (EPI) {
                v0.x = fmaxf(v0.x + bb0.x, 0.0f); v0.y = fmaxf(v0.y + bb0.y, 0.0f);
                v1.x = fmaxf(v1.x + bb1.x, 0.0f); v1.y = fmaxf(v1.y + bb1.y, 0.0f);
            }
            float* o = out + (size_t)grow * 128;
            *(float2*)(o + 2 * lane)      = v0;
            *(float2*)(o + 64 + 2 * lane) = v1;
        }
    }
}

// ---------------- CSR aggregation (128-wide) + BN stats ----------------
__global__ __launch_bounds__(256) void k_agg(const float* __restrict__ bias) {
    __shared__ float ss[128], sq[128];
    int t = threadIdx.x, lane = t & 31, warp = t >> 5;
    if (t < 128) { ss[t] = 0.f; sq[t] = 0.f; }
    __syncthreads();
    float4 bias4 = __ldg((const float4*)bias + lane);
    float4 sum4 = {0, 0, 0, 0}, sq4 = {0, 0, 0, 0};

    int n0 = (blockIdx.x * 8 + warp) * 8;
    for (int j = 0; j < 8; j++) {
        int n = n0 + j;
        if (n >= NN) break;
        float4 acc = bias4;
        int o0 = __ldg(&d_off[n]), o1 = __ldg(&d_off[n + 1]);
        int2 e0 = make_int2(0, 0), e1 = make_int2(0, 0);
        if (o0 < o1)     e0 = __ldg(&d_csr[o0]);
        if (o0 + 1 < o1) e1 = __ldg(&d_csr[o0 + 1]);
        for (int e = o0; e < o1; e++) {
            int2 e2 = make_int2(0, 0);
            if (e + 2 < o1) e2 = __ldg(&d_csr[e + 2]);
            float w = __int_as_float(e0.y);
            float4 v = __ldg((const float4*)(d_hw + (size_t)e0.x * 128) + lane);
            acc.x += v.x * w; acc.y += v.y * w; acc.z += v.z * w; acc.w += v.w * w;
            e0 = e1; e1 = e2;
        }
        float sn = __ldg(&d_dinv[n]);
        float sn2 = sn * sn;
        float4 vs = *((const float4*)(d_hw + (size_t)n * 128) + lane);
        acc.x += vs.x * sn2; acc.y += vs.y * sn2; acc.z += vs.z * sn2; acc.w += vs.w * sn2;

        *((float4*)(d_agg + (size_t)n * 128) + lane) = acc;
        sum4.x += acc.x; sum4.y += acc.y; sum4.z += acc.z; sum4.w += acc.w;
        sq4.x += acc.x * acc.x; sq4.y += acc.y * acc.y;
        sq4.z += acc.z * acc.z; sq4.w += acc.w * acc.w;
    }
    int c = lane * 4;
    atomicAdd(&ss[c + 0], sum4.x); atomicAdd(&ss[c + 1], sum4.y);
    atomicAdd(&ss[c + 2], sum4.z); atomicAdd(&ss[c + 3], sum4.w);
    atomicAdd(&sq[c + 0], sq4.x);  atomicAdd(&sq[c + 1], sq4.y);
    atomicAdd(&sq[c + 2], sq4.z);  atomicAdd(&sq[c + 3], sq4.w);
    __syncthreads();
    if (t < 128) {
        atomicAdd(&d_stats[t], ss[t]);
        atomicAdd(&d_stats[128 + t], sq[t]);
    }
}

__global__ void k_bn_params(const float* __restrict__ gamma, const float* __restrict__ beta) {
    int c = threadIdx.x;  // 128 threads
    float m = d_stats[c] * (1.0f / NN);
    float v = d_stats[128 + c] * (1.0f / NN) - m * m;
    float sc = gamma[c] * rsqrtf(v + 1e-5f);
    d_scale[c] = sc;
    d_shift[c] = beta[c] - m * sc;
}

// ---------------- fused BN-apply + pooling (final GCN layer) ----------------
__global__ __launch_bounds__(256) void k_bnpool(const void* __restrict__ batch) {
    int n = blockIdx.x * 8 + (threadIdx.x >> 5);
    if (n >= NN) return;
    int lane = threadIdx.x & 31;
    int g;
    if (d_is64) g = (int)((const long long*)batch)[n];
    else        g = ((const int*)batch)[n];
    g = min(max(g, 0), GG - 1);
    int c = lane * 4;
    float4 sc = *(const float4*)&d_scale[c];
    float4 sh = *(const float4*)&d_shift[c];
    float4 v = *((const float4*)(d_agg + (size_t)n * 128) + lane);
    v.x = fmaxf(v.x * sc.x + sh.x, 0.f);
    v.y = fmaxf(v.y * sc.y + sh.y, 0.f);
    v.z = fmaxf(v.z * sc.z + sh.z, 0.f);
    v.w = fmaxf(v.w * sc.w + sh.w, 0.f);
    red_add_v4(d_hp + (size_t)g * 128 + c, v.x, v.y, v.z, v.w);
}

// ---------------- head layer 0: l0 = relu(hp @ Wl0 + bl0) ----------------
__global__ __launch_bounds__(256) void k_head0(const float* __restrict__ W, const float* __restrict__ b) {
    __shared__ float in_s[8 * 128];
    int t = threadIdx.x;
    int g0 = blockIdx.x * 8;
    for (int i = t; i < (8 * 128) / 4; i += 256)
        ((float4*)in_s)[i] = ((const float4*)(d_hp + (size_t)g0 * 128))[i];
    __syncthreads();
    float acc[8] = {};
    for (int k = 0; k < 128; k++) {
        float w = W[k * 256 + t];
        #pragma unroll
        for (int r = 0; r < 8; r++) acc[r] += in_s[r * 128 + k] * w;
    }
    float bb = b[t];
    #pragma unroll
    for (int r = 0; r < 8; r++)
        d_l0[(size_t)(g0 + r) * 256 + t] = fmaxf(acc[r] + bb, 0.0f);
}

// ---------------- head GEMM: l1 = l0 @ W + b ----------------
__global__ __launch_bounds__(256) void k_headgemm(const float* __restrict__ W, const float* __restrict__ b) {
    __shared__ float in_s[8 * 256];
    int t = threadIdx.x;
    int g0 = blockIdx.x * 8;
    for (int i = t; i < (8 * 256) / 4; i += 256)
        ((float4*)in_s)[i] = ((const float4*)(d_l0 + (size_t)g0 * 256))[i];
    __syncthreads();
    float acc[8] = {};
    for (int k = 0; k < 256; k++) {
        float w = W[k * 256 + t];
        #pragma unroll
        for (int r = 0; r < 8; r++) acc[r] += in_s[r * 256 + k] * w;
    }
    float bb = b[t];
    #pragma unroll
    for (int r = 0; r < 8; r++)
        d_l1[(size_t)(g0 + r) * 256 + t] = acc[r] + bb;
}

// ---------------- head BN ----------------
__global__ __launch_bounds__(256) void k_lbn_stats(const float* __restrict__ gamma, const float* __restrict__ beta) {
    int c = blockIdx.x;
    int t = threadIdx.x;
    float ls = 0.f, lss = 0.f;
    for (int r = t; r < GG; r += 256) {
        float v = d_l1[(size_t)r * 256 + c];
        ls += v; lss += v * v;
    }
    __shared__ float ss[256], sq[256];
    ss[t] = ls; sq[t] = lss;
    __syncthreads();
    for (int o = 128; o > 0; o >>= 1) {
        if (t < o) { ss[t] += ss[t + o]; sq[t] += sq[t + o]; }
        __syncthreads();
    }
    if (t == 0) {
        float m = ss[0] * (1.0f / GG);
        float v = sq[0] * (1.0f / GG) - m * m;
        float sc = gamma[c] * rsqrtf(v + 1e-5f);
        d_lscale[c] = sc;
        d_lshift[c] = beta[c] - m * sc;
    }
}

__global__ void k_lbn_apply() {
    size_t idx = (size_t)blockIdx.x * 256 + threadIdx.x;
    if (idx < (size_t)GG * 256) {
        int c = (int)(idx & 255);
        d_l0[idx] = fmaxf(d_l1[idx] * d_lscale[c] + d_lshift[c], 0.0f);
    }
}

// ---------------- final: out = l0 @ Wout + bout ----------------
__global__ __launch_bounds__(64) void k_final(const float* __restrict__ Wout,
                                              const float* __restrict__ bout,
                                              float* __restrict__ out) {
    int r = blockIdx.x;
    int warp = threadIdx.x >> 5;
    int lane = threadIdx.x & 31;
    float s = 0.f;
    for (int k = lane; k < 256; k += 32)
        s += d_l0[(size_t)r * 256 + k] * Wout[k * 2 + warp];
    #pragma unroll
    for (int o = 16; o > 0; o >>= 1) s += __shfl_down_sync(0xffffffffu, s, o);
    if (lane == 0) out[r * 2 + warp] = s + bout[warp];
}

// ---------------- launch ----------------
extern "C" void kernel_launch(void* const* d_in, const int* in_sizes, int n_in,
                              void* d_out, int out_size) {
    const float* x     = (const float*)d_in[0];
    const void*  ei    = d_in[1];
    const void*  batch = d_in[2];
    int base = (n_in >= 18) ? 4 : 3;
    const float* W0      = (const float*)d_in[base + 0];
    const float* b0      = (const float*)d_in[base + 1];
    const float* Wg      = (const float*)d_in[base + 2];
    const float* bg      = (const float*)d_in[base + 3];
    const float* gamma_g = (const float*)d_in[base + 4];
    const float* beta_g  = (const float*)d_in[base + 5];
    const float* Wl0     = (const float*)d_in[base + 6];
    const float* bl0     = (const float*)d_in[base + 7];
    const float* Wl      = (const float*)d_in[base + 8];
    const float* bl      = (const float*)d_in[base + 9];
    const float* gamma_l = (const float*)d_in[base + 10];
    const float* beta_l  = (const float*)d_in[base + 11];
    const float* Wout    = (const float*)d_in[base + 12];
    const float* bout    = (const float*)d_in[base + 13];

    void *p_stats, *p_hp, *p_agg, *p_hw, *p_aggx;
    cudaGetSymbolAddress(&p_stats, d_stats);
    cudaGetSymbolAddress(&p_hp, d_hp);
    cudaGetSymbolAddress(&p_agg, d_agg);
    cudaGetSymbolAddress(&p_hw, d_hw);
    cudaGetSymbolAddress(&p_aggx, d_aggx);

    const int SMEM = 2 * 64 * 128 * 4;   // 64 KB (ws + hs) -> 3 CTAs/SM
    cudaFuncSetAttribute(k_gemm<64,  false, true>,  cudaFuncAttributeMaxDynamicSharedMemorySize, SMEM);
    cudaFuncSetAttribute(k_gemm<128, false, false>, cudaFuncAttributeMaxDynamicSharedMemorySize, SMEM);
    cudaFuncSetAttribute(k_gemm<128, true,  false>, cudaFuncAttributeMaxDynamicSharedMemorySize, SMEM);

    const int GEMM_GRID = (NN + 63) / 64;   // 782

    // preprocessing
    k_detect_init<<<NBLK, 256>>>((const int*)ei);
    k_prep_edges<<<2500, 256>>>(ei);
    k_scan1<<<NBLK, 256>>>();
    k_scan2<<<1, 256>>>();
    k_scan3<<<NBLK, 256>>>();
    k_csr_fill<<<2500, 256>>>();

    // layer 0: aggregate raw x (64-wide), GEMM with bias+relu epilogue -> h in d_agg
    k_aggx<<<6250, 256>>>(x);
    k_gemm<64, false, true><<<GEMM_GRID, 256, SMEM>>>((const float*)p_aggx, W0, b0, (float*)p_agg);

    // layers 1..4 (GCN + BN, BN applied lazily in next GEMM's input load)
    for (int i = 0; i < GD_; i++) {
        if (i == 0)
            k_gemm<128, false, false><<<GEMM_GRID, 256, SMEM>>>((const float*)p_agg, Wg, nullptr, (float*)p_hw);
        else
            k_gemm<128, true, false><<<GEMM_GRID, 256, SMEM>>>((const float*)p_agg,
                                                               Wg + (size_t)i * 128 * 128, nullptr, (float*)p_hw);
        cudaMemsetAsync(p_stats, 0, 2 * 128 * sizeof(float));
        k_agg<<<782, 256>>>(bg + (size_t)i * 128);
        k_bn_params<<<1, 128>>>(gamma_g + (size_t)i * 128, beta_g + (size_t)i * 128);
    }

    // fused BN-apply + pooling
    cudaMemsetAsync(p_hp, 0, (size_t)GG * 128 * sizeof(float));
    k_bnpool<<<6250, 256>>>(batch);

    // head
    k_head0<<<128, 256>>>(Wl0, bl0);
    for (int i = 0; i < LD_; i++) {
        k_headgemm<<<128, 256>>>(Wl + (size_t)i * 256 * 256, bl + (size_t)i * 256);
        k_lbn_stats<<<256, 256>>>(gamma_l + (size_t)i * 256, beta_l + (size_t)i * 256);
        k_lbn_apply<<<1024, 256>>>();
    }
    k_final<<<1024, 64>>>(Wout, bout, (float*)d_out);
}

// round 13
// speedup vs baseline: 1.5512x; 1.2142x over previous
#include <cuda_runtime.h>

// Problem constants (fixed shapes)
#define NN   50000
#define EE   640000
#define DIN  64
#define GB_  128
#define GD_  4
#define LB_  256
#define LD_  2
#define GG   1024
#define NBLK 196          // scan blocks: 196*256 >= NN

typedef unsigned long long ull;

// ---------------- device scratch ----------------
__device__ __align__(16) float d_dinv[NN];
__device__ int   d_ideg[NN];
__device__ int   d_off[NN + 1];
__device__ int   d_cursor[NN];
__device__ int   d_bsum[NBLK];
__device__ int   d_srcA[EE];
__device__ int   d_dstA[EE];
__device__ __align__(16) int2  d_csr[EE];      // {src, float_bits(enorm)}
__device__ __align__(16) float d_aggx[(size_t)NN * DIN];
__device__ __align__(16) float d_hw [(size_t)NN * GB_];
__device__ __align__(16) float d_agg[(size_t)NN * GB_];
__device__ __align__(16) float d_stats[2 * GB_];      // zero-init; reset by finalize
__device__ __align__(16) float d_scale[GB_];
__device__ __align__(16) float d_shift[GB_];
__device__ __align__(16) float d_hp[GG * GB_];
__device__ __align__(16) float d_l0[GG * LB_];
__device__ __align__(16) float d_l1[GG * LB_];
__device__ __align__(16) float d_lstats[2 * LB_];     // zero-init; reset by finalize
__device__ __align__(16) float d_lscale[LB_];
__device__ __align__(16) float d_lshift[LB_];
__device__ int d_ctr;     // k_agg finalize ticket
__device__ int d_lctr;    // headgemm finalize ticket
__device__ int d_is64;

// ---------------- helpers ----------------
__device__ __forceinline__ void red_add_v4(float* p, float a, float b, float c, float d) {
    asm volatile("red.global.add.v4.f32 [%0], {%1, %2, %3, %4};"
                 :: "l"(p), "f"(a), "f"(b), "f"(c), "f"(d) : "memory");
}
__device__ __forceinline__ ull ffma2(ull a, ull b, ull c) {
    ull r;
    asm("fma.rn.f32x2 %0, %1, %2, %3;" : "=l"(r) : "l"(a), "l"(b), "l"(c));
    return r;
}
__device__ __forceinline__ float redpair(ull v) {  // lo + hi
    float2 r;
    asm("mov.b64 {%0, %1}, %2;" : "=f"(r.x), "=f"(r.y) : "l"(v));
    return r.x + r.y;
}

// ---------------- preprocessing ----------------
// prep with inline dtype detection (per-block, redundant but cheap)
__global__ void k_prep(const void* __restrict__ ei) {
    __shared__ int s64;
    if (threadIdx.x == 0) {
        const int* p32 = (const int*)ei;
        int zeros = 0;
        for (int i = 0; i < 64; i++)
            if (p32[2 * i + 1] == 0) zeros++;
        s64 = (zeros >= 60) ? 1 : 0;
        if (blockIdx.x == 0) d_is64 = s64;
    }
    __syncthreads();
    int e = blockIdx.x * blockDim.x + threadIdx.x;
    if (e < EE) {
        int s, d;
        if (s64) {
            const long long* p = (const long long*)ei;
            s = (int)p[e];
            d = (int)p[EE + e];
        } else {
            const int* p = (const int*)ei;
            s = p[e];
            d = p[EE + e];
        }
        s = min(max(s, 0), NN - 1);
        d = min(max(d, 0), NN - 1);
        d_srcA[e] = s;
        d_dstA[e] = d;
        atomicAdd(&d_ideg[d], 1);
    }
}

// scan pass 1: per-block exclusive scan of ideg; also dinv, ideg reset, hp zero.
__global__ __launch_bounds__(256) void k_scan1() {
    __shared__ int wsum[8];
    int t = threadIdx.x, lane = t & 31, wid = t >> 5;
    int n = blockIdx.x * 256 + t;
    int gidx = n;
    if (gidx < GG * GB_ / 4) ((float4*)d_hp)[gidx] = make_float4(0.f, 0.f, 0.f, 0.f);
    int v = 0;
    if (n < NN) {
        v = d_ideg[n];
        d_ideg[n] = 0;                       // reset for next replay
        d_dinv[n] = rsqrtf((float)(1 + v));
    }
    int x = v;
    #pragma unroll
    for (int o = 1; o < 32; o <<= 1) {
        int y = __shfl_up_sync(0xffffffffu, x, o);
        if (lane >= o) x += y;
    }
    if (lane == 31) wsum[wid] = x;
    __syncthreads();
    if (wid == 0 && lane < 8) {
        int y = wsum[lane];
        #pragma unroll
        for (int o = 1; o < 8; o <<= 1) {
            int z = __shfl_up_sync(0xffu, y, o);
            if (lane >= o) y += z;
        }
        wsum[lane] = y;
    }
    __syncthreads();
    int excl = (wid > 0 ? wsum[wid - 1] : 0) + x - v;
    if (n < NN) d_off[n] = excl;
    if (t == 255) d_bsum[blockIdx.x] = wsum[7];
}

// scan pass 2: exclusive scan of block sums
__global__ __launch_bounds__(256) void k_scan2() {
    __shared__ int wsum[8];
    int t = threadIdx.x, lane = t & 31, wid = t >> 5;
    int v = (t < NBLK) ? d_bsum[t] : 0;
    int x = v;
    #pragma unroll
    for (int o = 1; o < 32; o <<= 1) {
        int y = __shfl_up_sync(0xffffffffu, x, o);
        if (lane >= o) x += y;
    }
    if (lane == 31) wsum[wid] = x;
    __syncthreads();
    if (wid == 0 && lane < 8) {
        int y = wsum[lane];
        #pragma unroll
        for (int o = 1; o < 8; o <<= 1) {
            int z = __shfl_up_sync(0xffu, y, o);
            if (lane >= o) y += z;
        }
        wsum[lane] = y;
    }
    __syncthreads();
    int excl = (wid > 0 ? wsum[wid - 1] : 0) + x - v;
    if (t < NBLK) d_bsum[t] = excl;
    if (t == 0) d_off[NN] = EE;
}

// scan pass 3: add block offsets, init cursor
__global__ void k_scan3() {
    int n = blockIdx.x * 256 + threadIdx.x;
    if (n < NN) {
        int o = d_off[n] + d_bsum[blockIdx.x];
        d_off[n] = o;
        d_cursor[n] = o;
    }
}

__global__ void k_csr_fill() {
    int e = blockIdx.x * blockDim.x + threadIdx.x;
    if (e < EE) {
        int s = d_srcA[e], d = d_dstA[e];
        int pos = atomicAdd(&d_cursor[d], 1);
        float w = d_dinv[s] * d_dinv[d];
        d_csr[pos] = make_int2(s, __float_as_int(w));
    }
}

// ---------------- layer-0 aggregation on raw x (64 wide) ----------------
__global__ __launch_bounds__(256) void k_aggx(const float* __restrict__ x) {
    int n = blockIdx.x * 8 + (threadIdx.x >> 5);
    if (n >= NN) return;
    int lane = threadIdx.x & 31;
    float sn = __ldg(&d_dinv[n]);
    float sn2 = sn * sn;
    float2 vs = __ldg((const float2*)(x + (size_t)n * DIN) + lane);
    float2 acc = make_float2(vs.x * sn2, vs.y * sn2);

    int o0 = __ldg(&d_off[n]), o1 = __ldg(&d_off[n + 1]);
    int2 e0 = make_int2(0, 0), e1 = make_int2(0, 0);
    if (o0 < o1)     e0 = __ldg(&d_csr[o0]);
    if (o0 + 1 < o1) e1 = __ldg(&d_csr[o0 + 1]);
    for (int e = o0; e < o1; e++) {
        int2 e2 = make_int2(0, 0);
        if (e + 2 < o1) e2 = __ldg(&d_csr[e + 2]);
        float w = __int_as_float(e0.y);
        float2 v = __ldg((const float2*)(x + (size_t)e0.x * DIN) + lane);
        acc.x += v.x * w; acc.y += v.y * w;
        e0 = e1; e1 = e2;
    }
    *((float2*)(d_aggx + (size_t)n * DIN) + lane) = acc;
}

// ---------------- node GEMM: out[N,128] = f(in)[N,K] @ W[K,128] ----------------
// K-parity split across f32x2 lanes: acc(ull) = (sum over even k, sum over odd k),
// reduced lo+hi at the end. h is read with NATURAL row-major broadcast LDS.64;
// weights are k-pair interleaved so one LDS.128 covers 2 output columns.
// Per warp-kk2 (2 k's): 2 LDS.128 + 8 broadcast LDS.64 + 32 FFMA2 -> FFMA2-pipe-bound.
// Smem 48KB/block.
template <int K, bool INBN, bool EPI>
__global__ __launch_bounds__(256) void k_gemm(const float* __restrict__ h,
                                              const float* __restrict__ W,
                                              const float* __restrict__ bias,
                                              float* __restrict__ out) {
    extern __shared__ float sm[];
    float2* wt = (float2*)sm;          // [32][128] float2: wt[kk2][c] = (W[2kk2][c], W[2kk2+1][c])
    float*  hs = sm + 32 * 128 * 2;    // [64][64] floats, row-major h chunk
    int t = threadIdx.x;
    int row0 = blockIdx.x * 64;
    int warp = t >> 5, lane = t & 31;
    int wr0 = warp * 8;

    ull acc[8][4] = {};   // [row][col: 2l, 2l+1, 64+2l, 64+2l+1]

    #pragma unroll
    for (int kc = 0; kc < K; kc += 64) {
        if (kc > 0) __syncthreads();
        // weights: interleave k-pairs. i -> kk2 = i>>5, c4 = (i&31)*4
        for (int i = t; i < 1024; i += 256) {
            int kk2 = i >> 5;
            int c4 = (i & 31) * 4;
            float4 lo = *(const float4*)(W + (size_t)(kc + 2 * kk2) * 128 + c4);
            float4 hi = *(const float4*)(W + (size_t)(kc + 2 * kk2 + 1) * 128 + c4);
            *(float4*)&wt[kk2 * 128 + c4]     = make_float4(lo.x, hi.x, lo.y, hi.y);
            *(float4*)&wt[kk2 * 128 + c4 + 2] = make_float4(lo.z, hi.z, lo.w, hi.w);
        }
        // h tile: straight row-major copy (coalesced), optional BN+relu
        for (int i = t; i < 1024; i += 256) {
            int row = i >> 4;
            int q = i & 15;
            int grow = row0 + row;
            float4 v = make_float4(0.f, 0.f, 0.f, 0.f);
            if (grow < NN) {
                v = *(const float4*)(h + (size_t)grow * K + kc + 4 * q);
                if (INBN) {
                    float4 sc = *(const float4*)&d_scale[kc + 4 * q];
                    float4 sh = *(const float4*)&d_shift[kc + 4 * q];
                    v.x = fmaxf(v.x * sc.x + sh.x, 0.0f);
                    v.y = fmaxf(v.y * sc.y + sh.y, 0.0f);
                    v.z = fmaxf(v.z * sc.z + sh.z, 0.0f);
                    v.w = fmaxf(v.w * sc.w + sh.w, 0.0f);
                }
            }
            *(float4*)&hs[row * 64 + 4 * q] = v;
        }
        __syncthreads();

        #pragma unroll 2
        for (int kk2 = 0; kk2 < 32; kk2++) {
            ulonglong2 wab = *(const ulonglong2*)&wt[kk2 * 128 + 2 * lane];        // cols 2l, 2l+1
            ulonglong2 wcd = *(const ulonglong2*)&wt[kk2 * 128 + 64 + 2 * lane];   // cols 64+2l, 64+2l+1
            #pragma unroll
            for (int r = 0; r < 8; r++) {
                ull hv = *(const ull*)&hs[(wr0 + r) * 64 + 2 * kk2];   // broadcast (h_even, h_odd)
                acc[r][0] = ffma2(hv, wab.x, acc[r][0]);
                acc[r][1] = ffma2(hv, wab.y, acc[r][1]);
                acc[r][2] = ffma2(hv, wcd.x, acc[r][2]);
                acc[r][3] = ffma2(hv, wcd.y, acc[r][3]);
            }
        }
    }

    float2 bb0, bb1;
    if (EPI) {
        bb0 = *(const float2*)&bias[2 * lane];
        bb1 = *(const float2*)&bias[64 + 2 * lane];
    }
    #pragma unroll
    for (int r = 0; r < 8; r++) {
        int grow = row0 + wr0 + r;
        if (grow < NN) {
            float2 v0 = make_float2(redpair(acc[r][0]), redpair(acc[r][1]));
            float2 v1 = make_float2(redpair(acc[r][2]), redpair(acc[r][3]));
            if (EPI) {
                v0.x = fmaxf(v0.x + bb0.x, 0.0f); v0.y = fmaxf(v0.y + bb0.y, 0.0f);
                v1.x = fmaxf(v1.x + bb1.x, 0.0f); v1.y = fmaxf(v1.y + bb1.y, 0.0f);
            }
            float* o = out + (size_t)grow * 128;
            *(float2*)(o + 2 * lane)      = v0;
            *(float2*)(o + 64 + 2 * lane) = v1;
        }
    }
}

// ---------------- CSR aggregation (128-wide) + BN stats + last-block finalize ----------------
__global__ __launch_bounds__(256) void k_agg(const float* __restrict__ bias,
                                             const float* __restrict__ gamma,
                                             const float* __restrict__ beta) {
    __shared__ float ss[128], sq[128];
    __shared__ int s_last;
    int t = threadIdx.x, lane = t & 31, warp = t >> 5;
    if (t < 128) { ss[t] = 0.f; sq[t] = 0.f; }
    __syncthreads();
    float4 bias4 = __ldg((const float4*)bias + lane);
    float4 sum4 = {0, 0, 0, 0}, sq4 = {0, 0, 0, 0};

    int n0 = (blockIdx.x * 8 + warp) * 8;
    for (int j = 0; j < 8; j++) {
        int n = n0 + j;
        if (n >= NN) break;
        float4 acc = bias4;
        int o0 = __ldg(&d_off[n]), o1 = __ldg(&d_off[n + 1]);
        int2 e0 = make_int2(0, 0), e1 = make_int2(0, 0);
        if (o0 < o1)     e0 = __ldg(&d_csr[o0]);
        if (o0 + 1 < o1) e1 = __ldg(&d_csr[o0 + 1]);
        for (int e = o0; e < o1; e++) {
            int2 e2 = make_int2(0, 0);
            if (e + 2 < o1) e2 = __ldg(&d_csr[e + 2]);
            float w = __int_as_float(e0.y);
            float4 v = __ldg((const float4*)(d_hw + (size_t)e0.x * 128) + lane);
            acc.x += v.x * w; acc.y += v.y * w; acc.z += v.z * w; acc.w += v.w * w;
            e0 = e1; e1 = e2;
        }
        float sn = __ldg(&d_dinv[n]);
        float sn2 = sn * sn;
        float4 vs = *((const float4*)(d_hw + (size_t)n * 128) + lane);
        acc.x += vs.x * sn2; acc.y += vs.y * sn2; acc.z += vs.z * sn2; acc.w += vs.w * sn2;

        *((float4*)(d_agg + (size_t)n * 128) + lane) = acc;
        sum4.x += acc.x; sum4.y += acc.y; sum4.z += acc.z; sum4.w += acc.w;
        sq4.x += acc.x * acc.x; sq4.y += acc.y * acc.y;
        sq4.z += acc.z * acc.z; sq4.w += acc.w * acc.w;
    }
    int c = lane * 4;
    atomicAdd(&ss[c + 0], sum4.x); atomicAdd(&ss[c + 1], sum4.y);
    atomicAdd(&ss[c + 2], sum4.z); atomicAdd(&ss[c + 3], sum4.w);
    atomicAdd(&sq[c + 0], sq4.x);  atomicAdd(&sq[c + 1], sq4.y);
    atomicAdd(&sq[c + 2], sq4.z);  atomicAdd(&sq[c + 3], sq4.w);
    __syncthreads();
    if (t < 128) {
        atomicAdd(&d_stats[t], ss[t]);
        atomicAdd(&d_stats[128 + t], sq[t]);
    }
    // last-block finalize: compute BN scale/shift, reset stats + ticket
    __threadfence();
    if (t == 0) s_last = (atomicAdd(&d_ctr, 1) == (int)gridDim.x - 1) ? 1 : 0;
    __syncthreads();
    if (s_last) {
        __threadfence();
        if (t < 128) {
            float m = d_stats[t] * (1.0f / NN);
            float v = d_stats[128 + t] * (1.0f / NN) - m * m;
            float sc = gamma[t] * rsqrtf(v + 1e-5f);
            d_scale[t] = sc;
            d_shift[t] = beta[t] - m * sc;
            d_stats[t] = 0.f;
            d_stats[128 + t] = 0.f;
        }
        if (t == 0) d_ctr = 0;
    }
}

// ---------------- fused BN-apply + pooling (final GCN layer) ----------------
__global__ __launch_bounds__(256) void k_bnpool(const void* __restrict__ batch) {
    int n = blockIdx.x * 8 + (threadIdx.x >> 5);
    if (n >= NN) return;
    int lane = threadIdx.x & 31;
    int g;
    if (d_is64) g = (int)((const long long*)batch)[n];
    else        g = ((const int*)batch)[n];
    g = min(max(g, 0), GG - 1);
    int c = lane * 4;
    float4 sc = *(const float4*)&d_scale[c];
    float4 sh = *(const float4*)&d_shift[c];
    float4 v = *((const float4*)(d_agg + (size_t)n * 128) + lane);
    v.x = fmaxf(v.x * sc.x + sh.x, 0.f);
    v.y = fmaxf(v.y * sc.y + sh.y, 0.f);
    v.z = fmaxf(v.z * sc.z + sh.z, 0.f);
    v.w = fmaxf(v.w * sc.w + sh.w, 0.f);
    red_add_v4(d_hp + (size_t)g * 128 + c, v.x, v.y, v.z, v.w);
}

// ---------------- head layer 0: l0 = relu(hp @ Wl0 + bl0) ----------------
__global__ __launch_bounds__(256) void k_head0(const float* __restrict__ W, const float* __restrict__ b) {
    __shared__ float in_s[8 * 128];
    int t = threadIdx.x;
    int g0 = blockIdx.x * 8;
    for (int i = t; i < (8 * 128) / 4; i += 256)
        ((float4*)in_s)[i] = ((const float4*)(d_hp + (size_t)g0 * 128))[i];
    __syncthreads();
    float acc[8] = {};
    for (int k = 0; k < 128; k++) {
        float w = W[k * 256 + t];
        #pragma unroll
        for (int r = 0; r < 8; r++) acc[r] += in_s[r * 128 + k] * w;
    }
    float bb = b[t];
    #pragma unroll
    for (int r = 0; r < 8; r++)
        d_l0[(size_t)(g0 + r) * 256 + t] = fmaxf(acc[r] + bb, 0.0f);
}

// ---------------- head GEMM: out = f(in) @ W + b, with fused BN stats + finalize ----------------
template <bool INBN>
__global__ __launch_bounds__(256) void k_headgemm(const float* __restrict__ in,
                                                  const float* __restrict__ W,
                                                  const float* __restrict__ b,
                                                  float* __restrict__ out,
                                                  const float* __restrict__ gamma,
                                                  const float* __restrict__ beta) {
    __shared__ float in_s[8 * 256];
    __shared__ int s_last;
    int t = threadIdx.x;
    int g0 = blockIdx.x * 8;
    for (int i = t; i < 512; i += 256) {
        float4 v = ((const float4*)(in + (size_t)g0 * 256))[i];
        if (INBN) {
            int c = (i * 4) & 255;
            float4 sc = *(const float4*)&d_lscale[c];
            float4 sh = *(const float4*)&d_lshift[c];
            v.x = fmaxf(v.x * sc.x + sh.x, 0.f);
            v.y = fmaxf(v.y * sc.y + sh.y, 0.f);
            v.z = fmaxf(v.z * sc.z + sh.z, 0.f);
            v.w = fmaxf(v.w * sc.w + sh.w, 0.f);
        }
        ((float4*)in_s)[i] = v;
    }
    __syncthreads();
    float acc[8] = {};
    for (int k = 0; k < 256; k++) {
        float w = W[k * 256 + t];
        #pragma unroll
        for (int r = 0; r < 8; r++) acc[r] += in_s[r * 256 + k] * w;
    }
    float bb = b[t];
    float ls = 0.f, lss = 0.f;
    #pragma unroll
    for (int r = 0; r < 8; r++) {
        float o = acc[r] + bb;
        out[(size_t)(g0 + r) * 256 + t] = o;
        ls += o; lss += o * o;
    }
    // stats over this block's 8 rows for column t (from registers)
    atomicAdd(&d_lstats[t], ls);
    atomicAdd(&d_lstats[256 + t], lss);
    __threadfence();
    if (t == 0) s_last = (atomicAdd(&d_lctr, 1) == (int)gridDim.x - 1) ? 1 : 0;
    __syncthreads();
    if (s_last) {
        __threadfence();
        float m = d_lstats[t] * (1.0f / GG);
        float v = d_lstats[256 + t] * (1.0f / GG) - m * m;
        float sc = gamma[t] * rsqrtf(v + 1e-5f);
        d_lscale[t] = sc;
        d_lshift[t] = beta[t] - m * sc;
        d_lstats[t] = 0.f;
        d_lstats[256 + t] = 0.f;
        if (t == 0) d_lctr = 0;
    }
}

// ---------------- final: out = relu(bn(in)) @ Wout + bout ----------------
__global__ __launch_bounds__(64) void k_final(const float* __restrict__ in,
                                              const float* __restrict__ Wout,
                                              const float* __restrict__ bout,
                                              float* __restrict__ out) {
    int r = blockIdx.x;
    int warp = threadIdx.x >> 5;
    int lane = threadIdx.x & 31;
    float s = 0.f;
    for (int k = lane; k < 256; k += 32) {
        float v = fmaxf(in[(size_t)r * 256 + k] * d_lscale[k] + d_lshift[k], 0.f);
        s += v * Wout[k * 2 + warp];
    }
    #pragma unroll
    for (int o = 16; o > 0; o >>= 1) s += __shfl_down_sync(0xffffffffu, s, o);
    if (lane == 0) out[r * 2 + warp] = s + bout[warp];
}

// ---------------- launch ----------------
extern "C" void kernel_launch(void* const* d_in, const int* in_sizes, int n_in,
                              void* d_out, int out_size) {
    const float* x     = (const float*)d_in[0];
    const void*  ei    = d_in[1];
    const void*  batch = d_in[2];
    int base = (n_in >= 18) ? 4 : 3;
    const float* W0      = (const float*)d_in[base + 0];
    const float* b0      = (const float*)d_in[base + 1];
    const float* Wg      = (const float*)d_in[base + 2];
    const float* bg      = (const float*)d_in[base + 3];
    const float* gamma_g = (const float*)d_in[base + 4];
    const float* beta_g  = (const float*)d_in[base + 5];
    const float* Wl0     = (const float*)d_in[base + 6];
    const float* bl0     = (const float*)d_in[base + 7];
    const float* Wl      = (const float*)d_in[base + 8];
    const float* bl      = (const float*)d_in[base + 9];
    const float* gamma_l = (const float*)d_in[base + 10];
    const float* beta_l  = (const float*)d_in[base + 11];
    const float* Wout    = (const float*)d_in[base + 12];
    const float* bout    = (const float*)d_in[base + 13];

    void *p_agg, *p_hw, *p_aggx, *p_l0, *p_l1;
    cudaGetSymbolAddress(&p_agg, d_agg);
    cudaGetSymbolAddress(&p_hw, d_hw);
    cudaGetSymbolAddress(&p_aggx, d_aggx);
    cudaGetSymbolAddress(&p_l0, d_l0);
    cudaGetSymbolAddress(&p_l1, d_l1);

    const int SMEM = (32 * 128 * 2 + 64 * 64) * 4;   // 48 KB (wt + hs)
    cudaFuncSetAttribute(k_gemm<64,  false, true>,  cudaFuncAttributeMaxDynamicSharedMemorySize, SMEM);
    cudaFuncSetAttribute(k_gemm<128, false, false>, cudaFuncAttributeMaxDynamicSharedMemorySize, SMEM);
    cudaFuncSetAttribute(k_gemm<128, true,  false>, cudaFuncAttributeMaxDynamicSharedMemorySize, SMEM);

    const int GEMM_GRID = (NN + 63) / 64;   // 782

    // preprocessing (5 kernels, no memsets)
    k_prep<<<2500, 256>>>(ei);
    k_scan1<<<NBLK, 256>>>();
    k_scan2<<<1, 256>>>();
    k_scan3<<<NBLK, 256>>>();
    k_csr_fill<<<2500, 256>>>();

    // layer 0: aggregate raw x (64-wide), GEMM with bias+relu epilogue -> h in d_agg
    k_aggx<<<6250, 256>>>(x);
    k_gemm<64, false, true><<<GEMM_GRID, 256, SMEM>>>((const float*)p_aggx, W0, b0, (float*)p_agg);

    // layers 1..4 (GCN; BN params computed by k_agg's last-block finalize,
    // applied lazily in the next consumer's input load)
    for (int i = 0; i < GD_; i++) {
        if (i == 0)
            k_gemm<128, false, false><<<GEMM_GRID, 256, SMEM>>>((const float*)p_agg, Wg, nullptr, (float*)p_hw);
        else
            k_gemm<128, true, false><<<GEMM_GRID, 256, SMEM>>>((const float*)p_agg,
                                                               Wg + (size_t)i * 128 * 128, nullptr, (float*)p_hw);
        k_agg<<<782, 256>>>(bg + (size_t)i * 128,
                            gamma_g + (size_t)i * 128, beta_g + (size_t)i * 128);
    }

    // fused BN-apply + pooling (hp zeroed in k_scan1)
    k_bnpool<<<6250, 256>>>(batch);

    // head: l0 = relu(hp@Wl0+b); hg0: l0->l1 (+stats0); hg1: l1->l0 applying bn0 (+stats1);
    // final applies bn1 inline.
    k_head0<<<128, 256>>>(Wl0, bl0);
    k_headgemm<false><<<128, 256>>>((const float*)p_l0, Wl, bl, (float*)p_l1,
                                    gamma_l, beta_l);
    k_headgemm<true><<<128, 256>>>((const float*)p_l1, Wl + (size_t)256 * 256, bl + 256, (float*)p_l0,
                                   gamma_l + 256, beta_l + 256);
    k_final<<<1024, 64>>>((const float*)p_l0, Wout, bout, (float*)d_out);
}